// round 15
// baseline (speedup 1.0000x reference)
#include <cuda_runtime.h>
#include <cuda_fp16.h>
#include <math.h>
#include <stdint.h>

#define B_   2
#define HW   65536
#define TABN 2048

// ---- scratch (static __device__ arrays: allocation-free) ----
__device__ __half g_P[(size_t)B_ * HW * 768];             // fp16 [b*HW][Qf(256)|Kf(256)|Vf(256)]
__device__ unsigned char g_Wfmt[(size_t)48 * 16384];       // weights fp16 swizzled: [jt*8+ch][128j][128B]
__device__ float g_kpe[4 * 256];
__device__ float g_vpe[4 * 256];
__device__ float g_qpeY[(TABN + 1) * 256];
__device__ float g_qpeX[(TABN + 1) * 256];

// ======================= helpers =======================

static __device__ __forceinline__ uint32_t smem_u32(const void* p) {
    uint32_t a;
    asm("{ .reg .u64 t; cvta.to.shared.u64 t, %1; cvt.u32.u64 %0, t; }" : "=r"(a) : "l"(p));
    return a;
}
static __device__ __forceinline__ uint32_t fh16(float v) {
    __half hb = __float2half_rn(v);
    return (uint32_t)*(uint16_t*)&hb;
}

static __device__ __forceinline__ void cp16(uint32_t dst, const void* src) {
    asm volatile("cp.async.cg.shared.global [%0], [%1], 16;" :: "r"(dst), "l"(src));
}
#define CP_COMMIT() asm volatile("cp.async.commit_group;" ::: "memory")

static __device__ __forceinline__ void ldsm4(uint32_t* r, uint32_t addr) {
    asm volatile("ldmatrix.sync.aligned.m8n8.x4.shared.b16 {%0,%1,%2,%3}, [%4];"
                 : "=r"(r[0]), "=r"(r[1]), "=r"(r[2]), "=r"(r[3]) : "r"(addr));
}

static __device__ __forceinline__ void mma16816(float* d, const uint32_t* a,
                                                uint32_t b0, uint32_t b1) {
    asm volatile(
        "mma.sync.aligned.m16n8k16.row.col.f32.f16.f16.f32 "
        "{%0,%1,%2,%3}, {%4,%5,%6,%7}, {%8,%9}, {%0,%1,%2,%3};"
        : "+f"(d[0]), "+f"(d[1]), "+f"(d[2]), "+f"(d[3])
        : "r"(a[0]), "r"(a[1]), "r"(a[2]), "r"(a[3]), "r"(b0), "r"(b1));
}

// ======================= weight prestage =======================

__global__ void prestage_w_kernel(const float* __restrict__ Wq,
                                  const float* __restrict__ Wk,
                                  const float* __restrict__ Wv) {
    int jt = blockIdx.x, ch = blockIdx.y;
    const float* W = (jt < 2) ? Wq : ((jt < 4) ? Wk : Wv);
    int jrb = (jt & 1) * 128;
    int tid = threadIdx.x;
    int j = tid >> 1, kh = tid & 1;
    const float* src = W + (size_t)(jrb + j) * 256 + ch * 32 + kh * 16;
    unsigned char* dst = g_Wfmt + (((size_t)jt * 8 + ch) << 14) + j * 128;
    uint32_t sw = (uint32_t)(j & 7);
    #pragma unroll
    for (int q = 0; q < 4; q++) {
        float4 v = *(const float4*)(src + q * 4);
        uint32_t h0 = fh16(v.x), h1 = fh16(v.y), h2 = fh16(v.z), h3 = fh16(v.w);
        int q8 = kh * 4 + q;
        uint32_t u = (uint32_t)(q8 >> 1);
        uint32_t half = (uint32_t)(q8 & 1) * 8;
        *(uint2*)(dst + (((u ^ sw) << 4) + half)) = make_uint2(h0 | (h1 << 16), h2 | (h3 << 16));
    }
}

// ======================= prep kernels =======================

__global__ void build_kvpe_kernel(const float* __restrict__ Wk, const float* __restrict__ bk,
                                  const float* __restrict__ Wv, const float* __restrict__ bv) {
    int uv = blockIdx.x;
    int j  = threadIdx.x;
    __shared__ float pe[256];
    {
        int half = j >> 7;
        int cc = j & 127;
        int m = cc >> 1;
        float coord = half ? (float)(uv & 1) : (float)(uv >> 1);
        float base = coord / (1.0f + 1e-6f) * 6.2831853071795864769f;
        float arg  = base * powf(10000.0f, -(float)(2 * m) / 128.0f);
        pe[j] = (cc & 1) ? cosf(arg) : sinf(arg);
    }
    __syncthreads();
    float sk = bk[j], sv = bv[j];
    const float* wkr = Wk + j * 256;
    const float* wvr = Wv + j * 256;
    #pragma unroll 4
    for (int c = 0; c < 256; c++) {
        float p = pe[c];
        sk = fmaf(p, wkr[c], sk);
        sv = fmaf(p, wvr[c], sv);
    }
    g_kpe[uv * 256 + j] = sk;
    g_vpe[uv * 256 + j] = sv;
}

__global__ void __launch_bounds__(256) qpetab_gemm_kernel(const float* __restrict__ Wq) {
    __shared__ float pe[32][132];
    __shared__ float Bs[32][128];

    int tid = threadIdx.x;
    int g0 = blockIdx.x * 32;
    int n0 = blockIdx.y * 128;
    int half = n0 >> 8;
    int jbase = n0 & 255;

    for (int i = tid; i < 32 * 128; i += 256) {
        int gg = i >> 7, c = i & 127;
        int m = c >> 1;
        float t = (float)(g0 + gg) / (float)TABN;
        float base = t / (2.0f + 1e-6f) * 6.2831853071795864769f;
        float arg  = base * powf(10000.0f, -(float)(2 * m) / 128.0f);
        pe[gg][c] = (c & 1) ? cosf(arg) : sinf(arg);
    }
    __syncthreads();

    int gthr = tid >> 5;
    int nthr = tid & 31;
    float acc[4][4];
    #pragma unroll
    for (int i = 0; i < 4; i++)
        #pragma unroll
        for (int j = 0; j < 4; j++) acc[i][j] = 0.f;

    int lj = tid >> 1, lkq = (tid & 1) * 16;
    const float* wsrc = Wq + (size_t)(jbase + lj) * 256 + half * 128 + lkq;

    for (int k0 = 0; k0 < 128; k0 += 32) {
        #pragma unroll
        for (int q = 0; q < 4; q++) {
            float4 v = *(const float4*)(wsrc + k0 + q * 4);
            Bs[lkq + q * 4 + 0][lj] = v.x;
            Bs[lkq + q * 4 + 1][lj] = v.y;
            Bs[lkq + q * 4 + 2][lj] = v.z;
            Bs[lkq + q * 4 + 3][lj] = v.w;
        }
        __syncthreads();
        #pragma unroll
        for (int kk = 0; kk < 32; kk++) {
            float a[4], b[4];
            #pragma unroll
            for (int i = 0; i < 4; i++) a[i] = pe[gthr * 4 + i][k0 + kk];
            *(float4*)&b[0] = *(const float4*)&Bs[kk][nthr * 4];
            #pragma unroll
            for (int i = 0; i < 4; i++)
                #pragma unroll
                for (int j = 0; j < 4; j++)
                    acc[i][j] = fmaf(a[i], b[j], acc[i][j]);
        }
        __syncthreads();
    }

    float* dst = half ? g_qpeX : g_qpeY;
    #pragma unroll
    for (int i = 0; i < 4; i++) {
        int g = g0 + gthr * 4 + i;
        if (g <= TABN) {
            *(float4*)&dst[(size_t)g * 256 + jbase + nthr * 4] =
                make_float4(acc[i][0], acc[i][1], acc[i][2], acc[i][3]);
        }
    }
}

// ======================= fused fp16 mma.sync projection GEMM (512 thr, occ 2) =======================
// A fp16 SMEM-resident (64KB). B: 3-deep cp.async ring (3 x 16KB).
// One barrier per chunk: wait_group -> syncthreads -> issue copy into freed buffer.

#define AOFF 0
#define BOFF 65536
#define SMEM_FUSED (65536 + 3 * 16384)

__global__ void __launch_bounds__(512, 2) proj_fused_kernel(const float* __restrict__ feat) {
    extern __shared__ char sm[];
    uint32_t smb = smem_u32(sm);
    int tid = threadIdx.x;
    int wid = tid >> 5, l = tid & 31;
    int wm = wid & 1, wn = wid >> 1;
    int mblk = blockIdx.x, b = blockIdx.y;

    // ---- A-prep: build fp16 swizzled A tile in SMEM ----
    {
        const float* srcb = feat + (size_t)b * 256 * HW + mblk * 128;
        float* stage = (float*)(sm + BOFF);        // 32 x 132 fp32, aliased with B ring
        int w8 = wid & 7;
        int pxh = (wid >> 3) * 64;
        uint32_t uh = (uint32_t)(w8 >> 1);
        uint32_t half = (uint32_t)(w8 & 1) * 8;
        for (int ch = 0; ch < 8; ch++) {
            #pragma unroll
            for (int p = 0; p < 2; p++) {
                int t = p * 512 + tid;
                int c = t >> 5, pxq = t & 31;
                float4 v = *(const float4*)(srcb + (size_t)(ch * 32 + c) * HW + pxq * 4);
                *(float4*)&stage[c * 132 + pxq * 4] = v;
            }
            __syncthreads();
            unsigned char* dst = (unsigned char*)sm + AOFF + (ch >> 1) * 16384;
            uint32_t ub = uh + (uint32_t)(ch & 1) * 4;
            #pragma unroll
            for (int p = 0; p < 2; p++) {
                int px = pxh + p * 32 + l;
                float v0 = stage[(w8 * 4 + 0) * 132 + px];
                float v1 = stage[(w8 * 4 + 1) * 132 + px];
                float v2 = stage[(w8 * 4 + 2) * 132 + px];
                float v3 = stage[(w8 * 4 + 3) * 132 + px];
                uint32_t h0 = fh16(v0), h1 = fh16(v1), h2 = fh16(v2), h3 = fh16(v3);
                uint2 hp = make_uint2(h0 | (h1 << 16), h2 | (h3 << 16));
                uint32_t rb = (uint32_t)px * 128;
                uint32_t sw = (uint32_t)(px & 7);
                *(uint2*)(dst + rb + (((ub ^ sw) << 4) + half)) = hp;
            }
            __syncthreads();
        }
    }

    // ---- mainloop: 48 B chunks (6 jt x 8 ch), 3-deep ring, 1 barrier/chunk ----
    #define COPY_B(gi, buf) do {                                                 \
        uint32_t _dB = smb + BOFF + (buf) * 16384;                               \
        const unsigned char* _sB = g_Wfmt + ((size_t)(gi) << 14);                \
        _Pragma("unroll")                                                        \
        for (int q = 0; q < 2; q++)                                              \
            cp16(_dB + tid * 16 + q * 8192, _sB + tid * 16 + q * 8192);          \
    } while (0)

    COPY_B(0, 0); CP_COMMIT();
    COPY_B(1, 1); CP_COMMIT();

    int ch16 = l >> 4;
    int r16 = l & 15;
    int rA = wm * 64 + (l >> 2);
    int colq = wn * 16 + (l & 3) * 2;

    int bufi = 0;  // (gi % 3)
    for (int jt = 0; jt < 6; jt++) {
        float d[4][2][4];
        #pragma unroll
        for (int i = 0; i < 4; i++)
            #pragma unroll
            for (int j = 0; j < 2; j++)
                #pragma unroll
                for (int k = 0; k < 4; k++) d[i][j][k] = 0.f;

        for (int ch = 0; ch < 8; ch++) {
            int gi = jt * 8 + ch;

            // wait for chunk gi (own groups), then barrier (visibility + frees buf gi-1)
            if (gi < 47) { asm volatile("cp.async.wait_group 1;" ::: "memory"); }
            else         { asm volatile("cp.async.wait_group 0;" ::: "memory"); }
            __syncthreads();

            // issue copy for gi+2 into the buffer chunk gi-1 just vacated
            int nxt = bufi + 2; if (nxt >= 3) nxt -= 3;
            if (gi + 2 < 48) { COPY_B(gi + 2, nxt); CP_COMMIT(); }

            uint32_t aB = smb + AOFF + (ch >> 1) * 16384;
            uint32_t au = (uint32_t)(ch & 1) * 4;
            uint32_t bB = smb + BOFF + bufi * 16384;

            #pragma unroll
            for (int s = 0; s < 2; s++) {
                uint32_t ah[4][4];
                #pragma unroll
                for (int mt = 0; mt < 4; mt++) {
                    int row = wm * 64 + mt * 16 + r16;
                    uint32_t rb = aB + row * 128;
                    uint32_t sw = (uint32_t)(row & 7);
                    ldsm4(ah[mt], rb + ((((au + (uint32_t)(s * 2 + ch16)) ^ sw) << 4)));
                }
                {
                    int row = wn * 16 + r16;
                    uint32_t rb = bB + row * 128;
                    uint32_t sw = (uint32_t)(row & 7);
                    uint32_t bh[4];
                    ldsm4(bh, rb + ((((uint32_t)(s * 2 + ch16)) ^ sw) << 4));
                    #pragma unroll
                    for (int sub = 0; sub < 2; sub++) {
                        uint32_t b0h = bh[sub], b1h = bh[2 + sub];
                        #pragma unroll
                        for (int mt = 0; mt < 4; mt++)
                            mma16816(d[mt][sub], ah[mt], b0h, b1h);
                    }
                }
            }

            if (++bufi >= 3) bufi = 0;
        }

        int colb = jt * 128 + colq;
        #pragma unroll
        for (int mt = 0; mt < 4; mt++) {
            #pragma unroll
            for (int nt = 0; nt < 2; nt++) {
                __half* p0 = g_P + (size_t)(b * HW + mblk * 128 + rA + mt * 16) * 768 + colb + nt * 8;
                *(__half2*)p0 = __floats2half2_rn(d[mt][nt][0], d[mt][nt][1]);
                *(__half2*)(p0 + 8 * 768) = __floats2half2_rn(d[mt][nt][2], d[mt][nt][3]);
            }
        }
    }
}

// ======================= attention epilogue (exact R12 body) =======================

static __device__ __forceinline__ void ld8(float* r, const float* p) {
    float4 v0 = *(const float4*)p;
    float4 v1 = *(const float4*)(p + 4);
    r[0] = v0.x; r[1] = v0.y; r[2] = v0.z; r[3] = v0.w;
    r[4] = v1.x; r[5] = v1.y; r[6] = v1.z; r[7] = v1.w;
}
static __device__ __forceinline__ void ld8h(float* r, const __half* p) {
    uint4 v = *(const uint4*)p;                  // 8 halves, 16B
    const __half2* h2 = reinterpret_cast<const __half2*>(&v);
    #pragma unroll
    for (int i = 0; i < 4; i++) {
        float2 f = __half22float2(h2[i]);
        r[2 * i] = f.x; r[2 * i + 1] = f.y;
    }
}

__global__ void __launch_bounds__(256) attn_epilogue_kernel(
    const float* __restrict__ offset, const float* __restrict__ bq,
    float* __restrict__ out) {
    __shared__ float s_kpe[4][256];
    __shared__ float s_vpe[4][256];
    __shared__ float s_out[256 * 33];

    int tid = threadIdx.x;
    int b = blockIdx.z, ty = blockIdx.y, tx0 = blockIdx.x * 32;

    for (int i = tid; i < 1024; i += 256) {
        ((float*)s_kpe)[i] = g_kpe[i];
        ((float*)s_vpe)[i] = g_vpe[i];
    }
    __syncthreads();

    int w = tid >> 5, l = tid & 31;
    int c0 = l * 8;
    const float scale = 0.17677669529663687f;   // 32^-0.5

    float qb[8];
    ld8(qb, bq + c0);

    for (int it = 0; it < 4; it++) {
        int px = w * 4 + it;
        int tx = tx0 + px;
        const float* offp = offset + (((size_t)(b * 256 + ty) * 256 + tx) * 2);
        float fx = (float)tx + offp[0];
        float fy = (float)ty + offp[1];
        float flY = floorf(fy), flX = floorf(fx);
        float dy = fy - flY, dx = fx - flX;
        int iy = (int)flY, ix = (int)flX;

        size_t rb[4];
        #pragma unroll
        for (int uv = 0; uv < 4; uv++) {
            int hh = iy + (uv >> 1); hh = min(max(hh, 0), 255);
            int ww = ix + (uv & 1);  ww = min(max(ww, 0), 255);
            rb[uv] = ((size_t)b * HW + (size_t)(hh * 256 + ww)) * 768;
        }

        float uy = dy * (float)TABN; int gy = (int)uy; float ry = uy - (float)gy;
        float ux = dx * (float)TABN; int gx = (int)ux; float rx = ux - (float)gx;
        float q[8], tA[8], tB[8], tC[8], tD[8];
        ld8(tA, g_qpeY + gy * 256 + c0);
        ld8(tB, g_qpeY + (gy + 1) * 256 + c0);
        ld8(tC, g_qpeX + gx * 256 + c0);
        ld8(tD, g_qpeX + (gx + 1) * 256 + c0);
        #pragma unroll
        for (int j = 0; j < 8; j++)
            q[j] = qb[j] + tA[j] + ry * (tB[j] - tA[j]) + tC[j] + rx * (tD[j] - tC[j]);
        #pragma unroll
        for (int uv = 0; uv < 4; uv++) {
            float f[8];
            ld8h(f, g_P + rb[uv] + c0);
            #pragma unroll
            for (int j = 0; j < 8; j++) q[j] = fmaf(0.25f, f[j], q[j]);
        }
        #pragma unroll
        for (int j = 0; j < 8; j++) q[j] *= scale;

        float lg[4];
        #pragma unroll
        for (int uv = 0; uv < 4; uv++) {
            float f[8], p[8];
            ld8h(f, g_P + rb[uv] + 256 + c0);
            ld8(p, &s_kpe[uv][c0]);
            float s = 0.f;
            #pragma unroll
            for (int j = 0; j < 8; j++) s = fmaf(q[j], f[j] + p[j], s);
            lg[uv] = s;
        }
        #pragma unroll
        for (int uv = 0; uv < 4; uv++) lg[uv] += __shfl_xor_sync(0xffffffffu, lg[uv], 1);
        #pragma unroll
        for (int uv = 0; uv < 4; uv++) lg[uv] += __shfl_xor_sync(0xffffffffu, lg[uv], 2);

        float mx = fmaxf(fmaxf(lg[0], lg[1]), fmaxf(lg[2], lg[3]));
        float e0 = __expf(lg[0] - mx), e1 = __expf(lg[1] - mx);
        float e2 = __expf(lg[2] - mx), e3 = __expf(lg[3] - mx);
        float inv = 1.0f / (e0 + e1 + e2 + e3);
        float at[4] = {e0 * inv, e1 * inv, e2 * inv, e3 * inv};

        float o[8];
        #pragma unroll
        for (int j = 0; j < 8; j++) o[j] = 0.f;
        #pragma unroll
        for (int uv = 0; uv < 4; uv++) {
            float f[8], p[8];
            ld8h(f, g_P + rb[uv] + 512 + c0);
            ld8(p, &s_vpe[uv][c0]);
            #pragma unroll
            for (int j = 0; j < 8; j++) o[j] = fmaf(at[uv], f[j] + p[j], o[j]);
        }
        #pragma unroll
        for (int j = 0; j < 8; j++) s_out[(c0 + j) * 33 + px] = o[j];
    }
    __syncthreads();

    for (int idx = tid; idx < 256 * 32; idx += 256) {
        int c = idx >> 5, px = idx & 31;
        out[((size_t)(b * 256 + c) * 256 + ty) * 256 + tx0 + px] = s_out[c * 33 + px];
    }
}

// ======================= launch =======================

extern "C" void kernel_launch(void* const* d_in, const int* in_sizes, int n_in,
                              void* d_out, int out_size) {
    (void)in_sizes; (void)n_in; (void)out_size;
    const float* feat   = (const float*)d_in[0];
    const float* offset = (const float*)d_in[1];
    const float* Wq     = (const float*)d_in[2];
    const float* bq     = (const float*)d_in[3];
    const float* Wk     = (const float*)d_in[4];
    const float* bk     = (const float*)d_in[5];
    const float* Wv     = (const float*)d_in[6];
    const float* bv     = (const float*)d_in[7];
    float* out = (float*)d_out;

    static int attr_set = 0;
    if (!attr_set) {
        cudaFuncSetAttribute(proj_fused_kernel,
                             cudaFuncAttributeMaxDynamicSharedMemorySize, SMEM_FUSED);
        attr_set = 1;
    }

    prestage_w_kernel<<<dim3(6, 8), 256>>>(Wq, Wk, Wv);
    build_kvpe_kernel<<<4, 256>>>(Wk, bk, Wv, bv);
    qpetab_gemm_kernel<<<dim3((TABN + 32) / 32, 4), 256>>>(Wq);
    proj_fused_kernel<<<dim3(512, B_), 512, SMEM_FUSED>>>(feat);
    attn_epilogue_kernel<<<dim3(8, 256, B_), 256>>>(offset, bq, out);
}

// round 16
// speedup vs baseline: 1.0542x; 1.0542x over previous
#include <cuda_runtime.h>
#include <cuda_fp16.h>
#include <math.h>
#include <stdint.h>

#define B_   2
#define HW   65536
#define TABN 2048

// ---- scratch (static __device__ arrays: allocation-free) ----
__device__ __half g_P[(size_t)B_ * HW * 768];             // fp16 [b*HW][Qf(256)|Kf(256)|Vf(256)]
__device__ unsigned char g_Wfmt[(size_t)48 * 16384];       // weights fp16 swizzled: [jt*8+ch][128j][128B]
__device__ float g_kpe[4 * 256];
__device__ float g_vpe[4 * 256];
__device__ __half g_qpeY[(TABN + 1) * 256];                // fp16 lerp tables
__device__ __half g_qpeX[(TABN + 1) * 256];

// ======================= helpers =======================

static __device__ __forceinline__ uint32_t smem_u32(const void* p) {
    uint32_t a;
    asm("{ .reg .u64 t; cvta.to.shared.u64 t, %1; cvt.u32.u64 %0, t; }" : "=r"(a) : "l"(p));
    return a;
}
static __device__ __forceinline__ uint32_t fh16(float v) {
    __half hb = __float2half_rn(v);
    return (uint32_t)*(uint16_t*)&hb;
}

static __device__ __forceinline__ void cp16(uint32_t dst, const void* src) {
    asm volatile("cp.async.cg.shared.global [%0], [%1], 16;" :: "r"(dst), "l"(src));
}
#define CP_COMMIT() asm volatile("cp.async.commit_group;" ::: "memory")

static __device__ __forceinline__ void ldsm4(uint32_t* r, uint32_t addr) {
    asm volatile("ldmatrix.sync.aligned.m8n8.x4.shared.b16 {%0,%1,%2,%3}, [%4];"
                 : "=r"(r[0]), "=r"(r[1]), "=r"(r[2]), "=r"(r[3]) : "r"(addr));
}

static __device__ __forceinline__ void mma16816(float* d, const uint32_t* a,
                                                uint32_t b0, uint32_t b1) {
    asm volatile(
        "mma.sync.aligned.m16n8k16.row.col.f32.f16.f16.f32 "
        "{%0,%1,%2,%3}, {%4,%5,%6,%7}, {%8,%9}, {%0,%1,%2,%3};"
        : "+f"(d[0]), "+f"(d[1]), "+f"(d[2]), "+f"(d[3])
        : "r"(a[0]), "r"(a[1]), "r"(a[2]), "r"(a[3]), "r"(b0), "r"(b1));
}

// ======================= weight prestage =======================

__global__ void prestage_w_kernel(const float* __restrict__ Wq,
                                  const float* __restrict__ Wk,
                                  const float* __restrict__ Wv) {
    int jt = blockIdx.x, ch = blockIdx.y;
    const float* W = (jt < 2) ? Wq : ((jt < 4) ? Wk : Wv);
    int jrb = (jt & 1) * 128;
    int tid = threadIdx.x;
    int j = tid >> 1, kh = tid & 1;
    const float* src = W + (size_t)(jrb + j) * 256 + ch * 32 + kh * 16;
    unsigned char* dst = g_Wfmt + (((size_t)jt * 8 + ch) << 14) + j * 128;
    uint32_t sw = (uint32_t)(j & 7);
    #pragma unroll
    for (int q = 0; q < 4; q++) {
        float4 v = *(const float4*)(src + q * 4);
        uint32_t h0 = fh16(v.x), h1 = fh16(v.y), h2 = fh16(v.z), h3 = fh16(v.w);
        int q8 = kh * 4 + q;
        uint32_t u = (uint32_t)(q8 >> 1);
        uint32_t half = (uint32_t)(q8 & 1) * 8;
        *(uint2*)(dst + (((u ^ sw) << 4) + half)) = make_uint2(h0 | (h1 << 16), h2 | (h3 << 16));
    }
}

// ======================= prep kernels =======================

__global__ void build_kvpe_kernel(const float* __restrict__ Wk, const float* __restrict__ bk,
                                  const float* __restrict__ Wv, const float* __restrict__ bv) {
    int uv = blockIdx.x;
    int j  = threadIdx.x;
    __shared__ float pe[256];
    {
        int half = j >> 7;
        int cc = j & 127;
        int m = cc >> 1;
        float coord = half ? (float)(uv & 1) : (float)(uv >> 1);
        float base = coord / (1.0f + 1e-6f) * 6.2831853071795864769f;
        float arg  = base * powf(10000.0f, -(float)(2 * m) / 128.0f);
        pe[j] = (cc & 1) ? cosf(arg) : sinf(arg);
    }
    __syncthreads();
    float sk = bk[j], sv = bv[j];
    const float* wkr = Wk + j * 256;
    const float* wvr = Wv + j * 256;
    #pragma unroll 4
    for (int c = 0; c < 256; c++) {
        float p = pe[c];
        sk = fmaf(p, wkr[c], sk);
        sv = fmaf(p, wvr[c], sv);
    }
    g_kpe[uv * 256 + j] = sk;
    g_vpe[uv * 256 + j] = sv;
}

__global__ void __launch_bounds__(256) qpetab_gemm_kernel(const float* __restrict__ Wq) {
    __shared__ float pe[32][132];
    __shared__ float Bs[32][128];

    int tid = threadIdx.x;
    int g0 = blockIdx.x * 32;
    int n0 = blockIdx.y * 128;
    int half = n0 >> 8;
    int jbase = n0 & 255;

    for (int i = tid; i < 32 * 128; i += 256) {
        int gg = i >> 7, c = i & 127;
        int m = c >> 1;
        float t = (float)(g0 + gg) / (float)TABN;
        float base = t / (2.0f + 1e-6f) * 6.2831853071795864769f;
        float arg  = base * powf(10000.0f, -(float)(2 * m) / 128.0f);
        pe[gg][c] = (c & 1) ? cosf(arg) : sinf(arg);
    }
    __syncthreads();

    int gthr = tid >> 5;
    int nthr = tid & 31;
    float acc[4][4];
    #pragma unroll
    for (int i = 0; i < 4; i++)
        #pragma unroll
        for (int j = 0; j < 4; j++) acc[i][j] = 0.f;

    int lj = tid >> 1, lkq = (tid & 1) * 16;
    const float* wsrc = Wq + (size_t)(jbase + lj) * 256 + half * 128 + lkq;

    for (int k0 = 0; k0 < 128; k0 += 32) {
        #pragma unroll
        for (int q = 0; q < 4; q++) {
            float4 v = *(const float4*)(wsrc + k0 + q * 4);
            Bs[lkq + q * 4 + 0][lj] = v.x;
            Bs[lkq + q * 4 + 1][lj] = v.y;
            Bs[lkq + q * 4 + 2][lj] = v.z;
            Bs[lkq + q * 4 + 3][lj] = v.w;
        }
        __syncthreads();
        #pragma unroll
        for (int kk = 0; kk < 32; kk++) {
            float a[4], b[4];
            #pragma unroll
            for (int i = 0; i < 4; i++) a[i] = pe[gthr * 4 + i][k0 + kk];
            *(float4*)&b[0] = *(const float4*)&Bs[kk][nthr * 4];
            #pragma unroll
            for (int i = 0; i < 4; i++)
                #pragma unroll
                for (int j = 0; j < 4; j++)
                    acc[i][j] = fmaf(a[i], b[j], acc[i][j]);
        }
        __syncthreads();
    }

    __half* dst = half ? g_qpeX : g_qpeY;
    #pragma unroll
    for (int i = 0; i < 4; i++) {
        int g = g0 + gthr * 4 + i;
        if (g <= TABN) {
            __half* p0 = dst + (size_t)g * 256 + jbase + nthr * 4;
            *(__half2*)p0       = __floats2half2_rn(acc[i][0], acc[i][1]);
            *(__half2*)(p0 + 2) = __floats2half2_rn(acc[i][2], acc[i][3]);
        }
    }
}

// ======================= fused fp16 mma.sync projection GEMM (512 thr, occ 2) =======================
// EXACT R12 mainloop: double-buffered B, 2 barriers/chunk (measured 239 us).

#define AOFF 0
#define BOFF 65536
#define SMEM_FUSED (65536 + 32768)

__global__ void __launch_bounds__(512, 2) proj_fused_kernel(const float* __restrict__ feat) {
    extern __shared__ char sm[];
    uint32_t smb = smem_u32(sm);
    int tid = threadIdx.x;
    int wid = tid >> 5, l = tid & 31;
    int wm = wid & 1, wn = wid >> 1;
    int mblk = blockIdx.x, b = blockIdx.y;

    // ---- A-prep: build fp16 swizzled A tile in SMEM ----
    {
        const float* srcb = feat + (size_t)b * 256 * HW + mblk * 128;
        float* stage = (float*)(sm + BOFF);
        int w8 = wid & 7;
        int pxh = (wid >> 3) * 64;
        uint32_t uh = (uint32_t)(w8 >> 1);
        uint32_t half = (uint32_t)(w8 & 1) * 8;
        for (int ch = 0; ch < 8; ch++) {
            #pragma unroll
            for (int p = 0; p < 2; p++) {
                int t = p * 512 + tid;
                int c = t >> 5, pxq = t & 31;
                float4 v = *(const float4*)(srcb + (size_t)(ch * 32 + c) * HW + pxq * 4);
                *(float4*)&stage[c * 132 + pxq * 4] = v;
            }
            __syncthreads();
            unsigned char* dst = (unsigned char*)sm + AOFF + (ch >> 1) * 16384;
            uint32_t ub = uh + (uint32_t)(ch & 1) * 4;
            #pragma unroll
            for (int p = 0; p < 2; p++) {
                int px = pxh + p * 32 + l;
                float v0 = stage[(w8 * 4 + 0) * 132 + px];
                float v1 = stage[(w8 * 4 + 1) * 132 + px];
                float v2 = stage[(w8 * 4 + 2) * 132 + px];
                float v3 = stage[(w8 * 4 + 3) * 132 + px];
                uint32_t h0 = fh16(v0), h1 = fh16(v1), h2 = fh16(v2), h3 = fh16(v3);
                uint2 hp = make_uint2(h0 | (h1 << 16), h2 | (h3 << 16));
                uint32_t rb = (uint32_t)px * 128;
                uint32_t sw = (uint32_t)(px & 7);
                *(uint2*)(dst + rb + (((ub ^ sw) << 4) + half)) = hp;
            }
            __syncthreads();
        }
    }

    // ---- mainloop: 48 B chunks (6 jt x 8 ch), double buffered ----
    #define COPY_B(gi, buf) do {                                                 \
        uint32_t _dB = smb + BOFF + (buf) * 16384;                               \
        const unsigned char* _sB = g_Wfmt + ((size_t)(gi) << 14);                \
        _Pragma("unroll")                                                        \
        for (int q = 0; q < 2; q++)                                              \
            cp16(_dB + tid * 16 + q * 8192, _sB + tid * 16 + q * 8192);          \
    } while (0)

    COPY_B(0, 0); CP_COMMIT();
    COPY_B(1, 1); CP_COMMIT();

    int ch16 = l >> 4;
    int r16 = l & 15;
    int rA = wm * 64 + (l >> 2);
    int colq = wn * 16 + (l & 3) * 2;

    for (int jt = 0; jt < 6; jt++) {
        float d[4][2][4];
        #pragma unroll
        for (int i = 0; i < 4; i++)
            #pragma unroll
            for (int j = 0; j < 2; j++)
                #pragma unroll
                for (int k = 0; k < 4; k++) d[i][j][k] = 0.f;

        for (int ch = 0; ch < 8; ch++) {
            int gi = jt * 8 + ch;
            if (gi == 47) { asm volatile("cp.async.wait_group 0;" ::: "memory"); }
            else          { asm volatile("cp.async.wait_group 1;" ::: "memory"); }
            __syncthreads();

            uint32_t aB = smb + AOFF + (ch >> 1) * 16384;
            uint32_t au = (uint32_t)(ch & 1) * 4;
            uint32_t bB = smb + BOFF + (gi & 1) * 16384;

            #pragma unroll
            for (int s = 0; s < 2; s++) {
                uint32_t ah[4][4];
                #pragma unroll
                for (int mt = 0; mt < 4; mt++) {
                    int row = wm * 64 + mt * 16 + r16;
                    uint32_t rb = aB + row * 128;
                    uint32_t sw = (uint32_t)(row & 7);
                    ldsm4(ah[mt], rb + ((((au + (uint32_t)(s * 2 + ch16)) ^ sw) << 4)));
                }
                {
                    int row = wn * 16 + r16;
                    uint32_t rb = bB + row * 128;
                    uint32_t sw = (uint32_t)(row & 7);
                    uint32_t bh[4];
                    ldsm4(bh, rb + ((((uint32_t)(s * 2 + ch16)) ^ sw) << 4));
                    #pragma unroll
                    for (int sub = 0; sub < 2; sub++) {
                        uint32_t b0h = bh[sub], b1h = bh[2 + sub];
                        #pragma unroll
                        for (int mt = 0; mt < 4; mt++)
                            mma16816(d[mt][sub], ah[mt], b0h, b1h);
                    }
                }
            }
            __syncthreads();
            if (gi + 2 < 48) { COPY_B(gi + 2, gi & 1); CP_COMMIT(); }
        }

        int colb = jt * 128 + colq;
        #pragma unroll
        for (int mt = 0; mt < 4; mt++) {
            #pragma unroll
            for (int nt = 0; nt < 2; nt++) {
                __half* p0 = g_P + (size_t)(b * HW + mblk * 128 + rA + mt * 16) * 768 + colb + nt * 8;
                *(__half2*)p0 = __floats2half2_rn(d[mt][nt][0], d[mt][nt][1]);
                *(__half2*)(p0 + 8 * 768) = __floats2half2_rn(d[mt][nt][2], d[mt][nt][3]);
            }
        }
    }
}

// ======================= attention epilogue (exact R12 body, fp16 qpe reads) =======================

static __device__ __forceinline__ void ld8(float* r, const float* p) {
    float4 v0 = *(const float4*)p;
    float4 v1 = *(const float4*)(p + 4);
    r[0] = v0.x; r[1] = v0.y; r[2] = v0.z; r[3] = v0.w;
    r[4] = v1.x; r[5] = v1.y; r[6] = v1.z; r[7] = v1.w;
}
static __device__ __forceinline__ void ld8h(float* r, const __half* p) {
    uint4 v = *(const uint4*)p;                  // 8 halves, 16B
    const __half2* h2 = reinterpret_cast<const __half2*>(&v);
    #pragma unroll
    for (int i = 0; i < 4; i++) {
        float2 f = __half22float2(h2[i]);
        r[2 * i] = f.x; r[2 * i + 1] = f.y;
    }
}

__global__ void __launch_bounds__(256) attn_epilogue_kernel(
    const float* __restrict__ offset, const float* __restrict__ bq,
    float* __restrict__ out) {
    __shared__ float s_kpe[4][256];
    __shared__ float s_vpe[4][256];
    __shared__ float s_out[256 * 33];

    int tid = threadIdx.x;
    int b = blockIdx.z, ty = blockIdx.y, tx0 = blockIdx.x * 32;

    for (int i = tid; i < 1024; i += 256) {
        ((float*)s_kpe)[i] = g_kpe[i];
        ((float*)s_vpe)[i] = g_vpe[i];
    }
    __syncthreads();

    int w = tid >> 5, l = tid & 31;
    int c0 = l * 8;
    const float scale = 0.17677669529663687f;   // 32^-0.5

    float qb[8];
    ld8(qb, bq + c0);

    for (int it = 0; it < 4; it++) {
        int px = w * 4 + it;
        int tx = tx0 + px;
        const float* offp = offset + (((size_t)(b * 256 + ty) * 256 + tx) * 2);
        float fx = (float)tx + offp[0];
        float fy = (float)ty + offp[1];
        float flY = floorf(fy), flX = floorf(fx);
        float dy = fy - flY, dx = fx - flX;
        int iy = (int)flY, ix = (int)flX;

        size_t rb[4];
        #pragma unroll
        for (int uv = 0; uv < 4; uv++) {
            int hh = iy + (uv >> 1); hh = min(max(hh, 0), 255);
            int ww = ix + (uv & 1);  ww = min(max(ww, 0), 255);
            rb[uv] = ((size_t)b * HW + (size_t)(hh * 256 + ww)) * 768;
        }

        float uy = dy * (float)TABN; int gy = (int)uy; float ry = uy - (float)gy;
        float ux = dx * (float)TABN; int gx = (int)ux; float rx = ux - (float)gx;
        float q[8], tA[8], tB[8], tC[8], tD[8];
        ld8h(tA, g_qpeY + gy * 256 + c0);
        ld8h(tB, g_qpeY + (gy + 1) * 256 + c0);
        ld8h(tC, g_qpeX + gx * 256 + c0);
        ld8h(tD, g_qpeX + (gx + 1) * 256 + c0);
        #pragma unroll
        for (int j = 0; j < 8; j++)
            q[j] = qb[j] + tA[j] + ry * (tB[j] - tA[j]) + tC[j] + rx * (tD[j] - tC[j]);
        #pragma unroll
        for (int uv = 0; uv < 4; uv++) {
            float f[8];
            ld8h(f, g_P + rb[uv] + c0);
            #pragma unroll
            for (int j = 0; j < 8; j++) q[j] = fmaf(0.25f, f[j], q[j]);
        }
        #pragma unroll
        for (int j = 0; j < 8; j++) q[j] *= scale;

        float lg[4];
        #pragma unroll
        for (int uv = 0; uv < 4; uv++) {
            float f[8], p[8];
            ld8h(f, g_P + rb[uv] + 256 + c0);
            ld8(p, &s_kpe[uv][c0]);
            float s = 0.f;
            #pragma unroll
            for (int j = 0; j < 8; j++) s = fmaf(q[j], f[j] + p[j], s);
            lg[uv] = s;
        }
        #pragma unroll
        for (int uv = 0; uv < 4; uv++) lg[uv] += __shfl_xor_sync(0xffffffffu, lg[uv], 1);
        #pragma unroll
        for (int uv = 0; uv < 4; uv++) lg[uv] += __shfl_xor_sync(0xffffffffu, lg[uv], 2);

        float mx = fmaxf(fmaxf(lg[0], lg[1]), fmaxf(lg[2], lg[3]));
        float e0 = __expf(lg[0] - mx), e1 = __expf(lg[1] - mx);
        float e2 = __expf(lg[2] - mx), e3 = __expf(lg[3] - mx);
        float inv = 1.0f / (e0 + e1 + e2 + e3);
        float at[4] = {e0 * inv, e1 * inv, e2 * inv, e3 * inv};

        float o[8];
        #pragma unroll
        for (int j = 0; j < 8; j++) o[j] = 0.f;
        #pragma unroll
        for (int uv = 0; uv < 4; uv++) {
            float f[8], p[8];
            ld8h(f, g_P + rb[uv] + 512 + c0);
            ld8(p, &s_vpe[uv][c0]);
            #pragma unroll
            for (int j = 0; j < 8; j++) o[j] = fmaf(at[uv], f[j] + p[j], o[j]);
        }
        #pragma unroll
        for (int j = 0; j < 8; j++) s_out[(c0 + j) * 33 + px] = o[j];
    }
    __syncthreads();

    for (int idx = tid; idx < 256 * 32; idx += 256) {
        int c = idx >> 5, px = idx & 31;
        out[((size_t)(b * 256 + c) * 256 + ty) * 256 + tx0 + px] = s_out[c * 33 + px];
    }
}

// ======================= launch =======================

extern "C" void kernel_launch(void* const* d_in, const int* in_sizes, int n_in,
                              void* d_out, int out_size) {
    (void)in_sizes; (void)n_in; (void)out_size;
    const float* feat   = (const float*)d_in[0];
    const float* offset = (const float*)d_in[1];
    const float* Wq     = (const float*)d_in[2];
    const float* bq     = (const float*)d_in[3];
    const float* Wk     = (const float*)d_in[4];
    const float* bk     = (const float*)d_in[5];
    const float* Wv     = (const float*)d_in[6];
    const float* bv     = (const float*)d_in[7];
    float* out = (float*)d_out;

    static int attr_set = 0;
    if (!attr_set) {
        cudaFuncSetAttribute(proj_fused_kernel,
                             cudaFuncAttributeMaxDynamicSharedMemorySize, SMEM_FUSED);
        attr_set = 1;
    }

    prestage_w_kernel<<<dim3(6, 8), 256>>>(Wq, Wk, Wv);
    build_kvpe_kernel<<<4, 256>>>(Wk, bk, Wv, bv);
    qpetab_gemm_kernel<<<dim3((TABN + 32) / 32, 4), 256>>>(Wq);
    proj_fused_kernel<<<dim3(512, B_), 512, SMEM_FUSED>>>(feat);
    attn_epilogue_kernel<<<dim3(8, 256, B_), 256>>>(offset, bq, out);
}

// round 17
// speedup vs baseline: 1.0783x; 1.0229x over previous
#include <cuda_runtime.h>
#include <cuda_fp16.h>
#include <math.h>
#include <stdint.h>

#define B_   2
#define HW   65536
#define TABN 2048

// ---- scratch (static __device__ arrays: allocation-free) ----
__device__ __half g_P[(size_t)B_ * HW * 768];             // fp16 [b*HW][Qf(256)|Kf(256)|Vf(256)]
__device__ unsigned char g_Wfmt[(size_t)48 * 16384];       // weights fp16 swizzled: [jt*8+ch][128j][128B]
__device__ float g_kpe[4 * 256];
__device__ float g_vpe[4 * 256];
__device__ __half g_qpeY[(TABN + 1) * 256];                // fp16 lerp tables
__device__ __half g_qpeX[(TABN + 1) * 256];

// ======================= helpers =======================

static __device__ __forceinline__ uint32_t smem_u32(const void* p) {
    uint32_t a;
    asm("{ .reg .u64 t; cvta.to.shared.u64 t, %1; cvt.u32.u64 %0, t; }" : "=r"(a) : "l"(p));
    return a;
}
static __device__ __forceinline__ uint32_t fh16(float v) {
    __half hb = __float2half_rn(v);
    return (uint32_t)*(uint16_t*)&hb;
}

static __device__ __forceinline__ void cp16(uint32_t dst, const void* src) {
    asm volatile("cp.async.cg.shared.global [%0], [%1], 16;" :: "r"(dst), "l"(src));
}
#define CP_COMMIT() asm volatile("cp.async.commit_group;" ::: "memory")

static __device__ __forceinline__ void ldsm4(uint32_t* r, uint32_t addr) {
    asm volatile("ldmatrix.sync.aligned.m8n8.x4.shared.b16 {%0,%1,%2,%3}, [%4];"
                 : "=r"(r[0]), "=r"(r[1]), "=r"(r[2]), "=r"(r[3]) : "r"(addr));
}

static __device__ __forceinline__ void mma16816(float* d, const uint32_t* a,
                                                uint32_t b0, uint32_t b1) {
    asm volatile(
        "mma.sync.aligned.m16n8k16.row.col.f32.f16.f16.f32 "
        "{%0,%1,%2,%3}, {%4,%5,%6,%7}, {%8,%9}, {%0,%1,%2,%3};"
        : "+f"(d[0]), "+f"(d[1]), "+f"(d[2]), "+f"(d[3])
        : "r"(a[0]), "r"(a[1]), "r"(a[2]), "r"(a[3]), "r"(b0), "r"(b1));
}

// ======================= weight prestage =======================

__global__ void prestage_w_kernel(const float* __restrict__ Wq,
                                  const float* __restrict__ Wk,
                                  const float* __restrict__ Wv) {
    int jt = blockIdx.x, ch = blockIdx.y;
    const float* W = (jt < 2) ? Wq : ((jt < 4) ? Wk : Wv);
    int jrb = (jt & 1) * 128;
    int tid = threadIdx.x;
    int j = tid >> 1, kh = tid & 1;
    const float* src = W + (size_t)(jrb + j) * 256 + ch * 32 + kh * 16;
    unsigned char* dst = g_Wfmt + (((size_t)jt * 8 + ch) << 14) + j * 128;
    uint32_t sw = (uint32_t)(j & 7);
    #pragma unroll
    for (int q = 0; q < 4; q++) {
        float4 v = *(const float4*)(src + q * 4);
        uint32_t h0 = fh16(v.x), h1 = fh16(v.y), h2 = fh16(v.z), h3 = fh16(v.w);
        int q8 = kh * 4 + q;
        uint32_t u = (uint32_t)(q8 >> 1);
        uint32_t half = (uint32_t)(q8 & 1) * 8;
        *(uint2*)(dst + (((u ^ sw) << 4) + half)) = make_uint2(h0 | (h1 << 16), h2 | (h3 << 16));
    }
}

// ======================= prep kernels =======================

__global__ void build_kvpe_kernel(const float* __restrict__ Wk, const float* __restrict__ bk,
                                  const float* __restrict__ Wv, const float* __restrict__ bv) {
    int uv = blockIdx.x;
    int j  = threadIdx.x;
    __shared__ float pe[256];
    {
        int half = j >> 7;
        int cc = j & 127;
        int m = cc >> 1;
        float coord = half ? (float)(uv & 1) : (float)(uv >> 1);
        float base = coord / (1.0f + 1e-6f) * 6.2831853071795864769f;
        float arg  = base * powf(10000.0f, -(float)(2 * m) / 128.0f);
        pe[j] = (cc & 1) ? cosf(arg) : sinf(arg);
    }
    __syncthreads();
    float sk = bk[j], sv = bv[j];
    const float* wkr = Wk + j * 256;
    const float* wvr = Wv + j * 256;
    #pragma unroll 4
    for (int c = 0; c < 256; c++) {
        float p = pe[c];
        sk = fmaf(p, wkr[c], sk);
        sv = fmaf(p, wvr[c], sv);
    }
    g_kpe[uv * 256 + j] = sk;
    g_vpe[uv * 256 + j] = sv;
}

__global__ void __launch_bounds__(256) qpetab_gemm_kernel(const float* __restrict__ Wq) {
    __shared__ float pe[32][132];
    __shared__ float Bs[32][128];

    int tid = threadIdx.x;
    int g0 = blockIdx.x * 32;
    int n0 = blockIdx.y * 128;
    int half = n0 >> 8;
    int jbase = n0 & 255;

    for (int i = tid; i < 32 * 128; i += 256) {
        int gg = i >> 7, c = i & 127;
        int m = c >> 1;
        float t = (float)(g0 + gg) / (float)TABN;
        float base = t / (2.0f + 1e-6f) * 6.2831853071795864769f;
        float arg  = base * powf(10000.0f, -(float)(2 * m) / 128.0f);
        pe[gg][c] = (c & 1) ? cosf(arg) : sinf(arg);
    }
    __syncthreads();

    int gthr = tid >> 5;
    int nthr = tid & 31;
    float acc[4][4];
    #pragma unroll
    for (int i = 0; i < 4; i++)
        #pragma unroll
        for (int j = 0; j < 4; j++) acc[i][j] = 0.f;

    int lj = tid >> 1, lkq = (tid & 1) * 16;
    const float* wsrc = Wq + (size_t)(jbase + lj) * 256 + half * 128 + lkq;

    for (int k0 = 0; k0 < 128; k0 += 32) {
        #pragma unroll
        for (int q = 0; q < 4; q++) {
            float4 v = *(const float4*)(wsrc + k0 + q * 4);
            Bs[lkq + q * 4 + 0][lj] = v.x;
            Bs[lkq + q * 4 + 1][lj] = v.y;
            Bs[lkq + q * 4 + 2][lj] = v.z;
            Bs[lkq + q * 4 + 3][lj] = v.w;
        }
        __syncthreads();
        #pragma unroll
        for (int kk = 0; kk < 32; kk++) {
            float a[4], b[4];
            #pragma unroll
            for (int i = 0; i < 4; i++) a[i] = pe[gthr * 4 + i][k0 + kk];
            *(float4*)&b[0] = *(const float4*)&Bs[kk][nthr * 4];
            #pragma unroll
            for (int i = 0; i < 4; i++)
                #pragma unroll
                for (int j = 0; j < 4; j++)
                    acc[i][j] = fmaf(a[i], b[j], acc[i][j]);
        }
        __syncthreads();
    }

    __half* dst = half ? g_qpeX : g_qpeY;
    #pragma unroll
    for (int i = 0; i < 4; i++) {
        int g = g0 + gthr * 4 + i;
        if (g <= TABN) {
            __half* p0 = dst + (size_t)g * 256 + jbase + nthr * 4;
            *(__half2*)p0       = __floats2half2_rn(acc[i][0], acc[i][1]);
            *(__half2*)(p0 + 2) = __floats2half2_rn(acc[i][2], acc[i][3]);
        }
    }
}

// ======================= fused fp16 mma.sync projection GEMM (512 thr, occ 2) =======================

#define AOFF 0
#define BOFF 65536
#define SMEM_FUSED (65536 + 32768)

__global__ void __launch_bounds__(512, 2) proj_fused_kernel(const float* __restrict__ feat) {
    extern __shared__ char sm[];
    uint32_t smb = smem_u32(sm);
    int tid = threadIdx.x;
    int wid = tid >> 5, l = tid & 31;
    int wm = wid & 1, wn = wid >> 1;
    int mblk = blockIdx.x, b = blockIdx.y;

    // ---- A-prep: build fp16 swizzled A tile in SMEM ----
    {
        const float* srcb = feat + (size_t)b * 256 * HW + mblk * 128;
        float* stage = (float*)(sm + BOFF);
        int w8 = wid & 7;
        int pxh = (wid >> 3) * 64;
        uint32_t uh = (uint32_t)(w8 >> 1);
        uint32_t half = (uint32_t)(w8 & 1) * 8;
        for (int ch = 0; ch < 8; ch++) {
            #pragma unroll
            for (int p = 0; p < 2; p++) {
                int t = p * 512 + tid;
                int c = t >> 5, pxq = t & 31;
                float4 v = *(const float4*)(srcb + (size_t)(ch * 32 + c) * HW + pxq * 4);
                *(float4*)&stage[c * 132 + pxq * 4] = v;
            }
            __syncthreads();
            unsigned char* dst = (unsigned char*)sm + AOFF + (ch >> 1) * 16384;
            uint32_t ub = uh + (uint32_t)(ch & 1) * 4;
            #pragma unroll
            for (int p = 0; p < 2; p++) {
                int px = pxh + p * 32 + l;
                float v0 = stage[(w8 * 4 + 0) * 132 + px];
                float v1 = stage[(w8 * 4 + 1) * 132 + px];
                float v2 = stage[(w8 * 4 + 2) * 132 + px];
                float v3 = stage[(w8 * 4 + 3) * 132 + px];
                uint32_t h0 = fh16(v0), h1 = fh16(v1), h2 = fh16(v2), h3 = fh16(v3);
                uint2 hp = make_uint2(h0 | (h1 << 16), h2 | (h3 << 16));
                uint32_t rb = (uint32_t)px * 128;
                uint32_t sw = (uint32_t)(px & 7);
                *(uint2*)(dst + rb + (((ub ^ sw) << 4) + half)) = hp;
            }
            __syncthreads();
        }
    }

    // ---- mainloop: 48 B chunks (6 jt x 8 ch), double buffered ----
    #define COPY_B(gi, buf) do {                                                 \
        uint32_t _dB = smb + BOFF + (buf) * 16384;                               \
        const unsigned char* _sB = g_Wfmt + ((size_t)(gi) << 14);                \
        _Pragma("unroll")                                                        \
        for (int q = 0; q < 2; q++)                                              \
            cp16(_dB + tid * 16 + q * 8192, _sB + tid * 16 + q * 8192);          \
    } while (0)

    COPY_B(0, 0); CP_COMMIT();
    COPY_B(1, 1); CP_COMMIT();

    int ch16 = l >> 4;
    int r16 = l & 15;
    int rA = wm * 64 + (l >> 2);
    int colq = wn * 16 + (l & 3) * 2;

    for (int jt = 0; jt < 6; jt++) {
        float d[4][2][4];
        #pragma unroll
        for (int i = 0; i < 4; i++)
            #pragma unroll
            for (int j = 0; j < 2; j++)
                #pragma unroll
                for (int k = 0; k < 4; k++) d[i][j][k] = 0.f;

        for (int ch = 0; ch < 8; ch++) {
            int gi = jt * 8 + ch;
            if (gi == 47) { asm volatile("cp.async.wait_group 0;" ::: "memory"); }
            else          { asm volatile("cp.async.wait_group 1;" ::: "memory"); }
            __syncthreads();

            uint32_t aB = smb + AOFF + (ch >> 1) * 16384;
            uint32_t au = (uint32_t)(ch & 1) * 4;
            uint32_t bB = smb + BOFF + (gi & 1) * 16384;

            #pragma unroll
            for (int s = 0; s < 2; s++) {
                uint32_t ah[4][4];
                #pragma unroll
                for (int mt = 0; mt < 4; mt++) {
                    int row = wm * 64 + mt * 16 + r16;
                    uint32_t rb = aB + row * 128;
                    uint32_t sw = (uint32_t)(row & 7);
                    ldsm4(ah[mt], rb + ((((au + (uint32_t)(s * 2 + ch16)) ^ sw) << 4)));
                }
                {
                    int row = wn * 16 + r16;
                    uint32_t rb = bB + row * 128;
                    uint32_t sw = (uint32_t)(row & 7);
                    uint32_t bh[4];
                    ldsm4(bh, rb + ((((uint32_t)(s * 2 + ch16)) ^ sw) << 4));
                    #pragma unroll
                    for (int sub = 0; sub < 2; sub++) {
                        uint32_t b0h = bh[sub], b1h = bh[2 + sub];
                        #pragma unroll
                        for (int mt = 0; mt < 4; mt++)
                            mma16816(d[mt][sub], ah[mt], b0h, b1h);
                    }
                }
            }
            __syncthreads();
            if (gi + 2 < 48) { COPY_B(gi + 2, gi & 1); CP_COMMIT(); }
        }

        int colb = jt * 128 + colq;
        #pragma unroll
        for (int mt = 0; mt < 4; mt++) {
            #pragma unroll
            for (int nt = 0; nt < 2; nt++) {
                __half* p0 = g_P + (size_t)(b * HW + mblk * 128 + rA + mt * 16) * 768 + colb + nt * 8;
                *(__half2*)p0 = __floats2half2_rn(d[mt][nt][0], d[mt][nt][1]);
                *(__half2*)(p0 + 8 * 768) = __floats2half2_rn(d[mt][nt][2], d[mt][nt][3]);
            }
        }
    }
}

// ======================= attention epilogue (R16 body + smem-staged offsets) =======================

static __device__ __forceinline__ void ld8(float* r, const float* p) {
    float4 v0 = *(const float4*)p;
    float4 v1 = *(const float4*)(p + 4);
    r[0] = v0.x; r[1] = v0.y; r[2] = v0.z; r[3] = v0.w;
    r[4] = v1.x; r[5] = v1.y; r[6] = v1.z; r[7] = v1.w;
}
static __device__ __forceinline__ void ld8h(float* r, const __half* p) {
    uint4 v = *(const uint4*)p;                  // 8 halves, 16B
    const __half2* h2 = reinterpret_cast<const __half2*>(&v);
    #pragma unroll
    for (int i = 0; i < 4; i++) {
        float2 f = __half22float2(h2[i]);
        r[2 * i] = f.x; r[2 * i + 1] = f.y;
    }
}

__global__ void __launch_bounds__(256) attn_epilogue_kernel(
    const float* __restrict__ offset, const float* __restrict__ bq,
    float* __restrict__ out) {
    __shared__ float s_kpe[4][256];
    __shared__ float s_vpe[4][256];
    __shared__ float s_off[64];          // 32 px x (dx, dy)
    __shared__ float s_out[256 * 33];

    int tid = threadIdx.x;
    int b = blockIdx.z, ty = blockIdx.y, tx0 = blockIdx.x * 32;

    // stage this block's 32 offset pairs (one coalesced 256B load)
    if (tid < 64) {
        s_off[tid] = offset[(((size_t)(b * 256 + ty) * 256 + tx0) * 2) + tid];
    }
    for (int i = tid; i < 1024; i += 256) {
        ((float*)s_kpe)[i] = g_kpe[i];
        ((float*)s_vpe)[i] = g_vpe[i];
    }
    __syncthreads();

    int w = tid >> 5, l = tid & 31;
    int c0 = l * 8;
    const float scale = 0.17677669529663687f;   // 32^-0.5

    float qb[8];
    ld8(qb, bq + c0);

    for (int it = 0; it < 4; it++) {
        int px = w * 4 + it;
        int tx = tx0 + px;
        float fx = (float)tx + s_off[px * 2 + 0];
        float fy = (float)ty + s_off[px * 2 + 1];
        float flY = floorf(fy), flX = floorf(fx);
        float dy = fy - flY, dx = fx - flX;
        int iy = (int)flY, ix = (int)flX;

        size_t rb[4];
        #pragma unroll
        for (int uv = 0; uv < 4; uv++) {
            int hh = iy + (uv >> 1); hh = min(max(hh, 0), 255);
            int ww = ix + (uv & 1);  ww = min(max(ww, 0), 255);
            rb[uv] = ((size_t)b * HW + (size_t)(hh * 256 + ww)) * 768;
        }

        float uy = dy * (float)TABN; int gy = (int)uy; float ry = uy - (float)gy;
        float ux = dx * (float)TABN; int gx = (int)ux; float rx = ux - (float)gx;
        float q[8], tA[8], tB[8], tC[8], tD[8];
        ld8h(tA, g_qpeY + gy * 256 + c0);
        ld8h(tB, g_qpeY + (gy + 1) * 256 + c0);
        ld8h(tC, g_qpeX + gx * 256 + c0);
        ld8h(tD, g_qpeX + (gx + 1) * 256 + c0);
        #pragma unroll
        for (int j = 0; j < 8; j++)
            q[j] = qb[j] + tA[j] + ry * (tB[j] - tA[j]) + tC[j] + rx * (tD[j] - tC[j]);
        #pragma unroll
        for (int uv = 0; uv < 4; uv++) {
            float f[8];
            ld8h(f, g_P + rb[uv] + c0);
            #pragma unroll
            for (int j = 0; j < 8; j++) q[j] = fmaf(0.25f, f[j], q[j]);
        }
        #pragma unroll
        for (int j = 0; j < 8; j++) q[j] *= scale;

        float lg[4];
        #pragma unroll
        for (int uv = 0; uv < 4; uv++) {
            float f[8], p[8];
            ld8h(f, g_P + rb[uv] + 256 + c0);
            ld8(p, &s_kpe[uv][c0]);
            float s = 0.f;
            #pragma unroll
            for (int j = 0; j < 8; j++) s = fmaf(q[j], f[j] + p[j], s);
            lg[uv] = s;
        }
        #pragma unroll
        for (int uv = 0; uv < 4; uv++) lg[uv] += __shfl_xor_sync(0xffffffffu, lg[uv], 1);
        #pragma unroll
        for (int uv = 0; uv < 4; uv++) lg[uv] += __shfl_xor_sync(0xffffffffu, lg[uv], 2);

        float mx = fmaxf(fmaxf(lg[0], lg[1]), fmaxf(lg[2], lg[3]));
        float e0 = __expf(lg[0] - mx), e1 = __expf(lg[1] - mx);
        float e2 = __expf(lg[2] - mx), e3 = __expf(lg[3] - mx);
        float inv = 1.0f / (e0 + e1 + e2 + e3);
        float at[4] = {e0 * inv, e1 * inv, e2 * inv, e3 * inv};

        float o[8];
        #pragma unroll
        for (int j = 0; j < 8; j++) o[j] = 0.f;
        #pragma unroll
        for (int uv = 0; uv < 4; uv++) {
            float f[8], p[8];
            ld8h(f, g_P + rb[uv] + 512 + c0);
            ld8(p, &s_vpe[uv][c0]);
            #pragma unroll
            for (int j = 0; j < 8; j++) o[j] = fmaf(at[uv], f[j] + p[j], o[j]);
        }
        #pragma unroll
        for (int j = 0; j < 8; j++) s_out[(c0 + j) * 33 + px] = o[j];
    }
    __syncthreads();

    for (int idx = tid; idx < 256 * 32; idx += 256) {
        int c = idx >> 5, px = idx & 31;
        out[((size_t)(b * 256 + c) * 256 + ty) * 256 + tx0 + px] = s_out[c * 33 + px];
    }
}

// ======================= launch =======================

extern "C" void kernel_launch(void* const* d_in, const int* in_sizes, int n_in,
                              void* d_out, int out_size) {
    (void)in_sizes; (void)n_in; (void)out_size;
    const float* feat   = (const float*)d_in[0];
    const float* offset = (const float*)d_in[1];
    const float* Wq     = (const float*)d_in[2];
    const float* bq     = (const float*)d_in[3];
    const float* Wk     = (const float*)d_in[4];
    const float* bk     = (const float*)d_in[5];
    const float* Wv     = (const float*)d_in[6];
    const float* bv     = (const float*)d_in[7];
    float* out = (float*)d_out;

    static int attr_set = 0;
    if (!attr_set) {
        cudaFuncSetAttribute(proj_fused_kernel,
                             cudaFuncAttributeMaxDynamicSharedMemorySize, SMEM_FUSED);
        attr_set = 1;
    }

    prestage_w_kernel<<<dim3(6, 8), 256>>>(Wq, Wk, Wv);
    build_kvpe_kernel<<<4, 256>>>(Wk, bk, Wv, bv);
    qpetab_gemm_kernel<<<dim3((TABN + 32) / 32, 4), 256>>>(Wq);
    proj_fused_kernel<<<dim3(512, B_), 512, SMEM_FUSED>>>(feat);
    attn_epilogue_kernel<<<dim3(8, 256, B_), 256>>>(offset, bq, out);
}